// round 6
// baseline (speedup 1.0000x reference)
#include <cuda_runtime.h>
#include <math.h>

// Problem constants (fixed by reference_code)
#define HP   2080            // padded height = H + 2*margin
#define WP   2080            // padded width
#define OW   2048            // output width
#define OH   2048            // output height
#define MARG 16
#define RAD  16              // truncation radius of real-space Gaussian (sigma_x ~ 3.18 px)
#define KW   (2*RAD + 1)     // 33 taps
#define SIG  0.05

// Scratch (device globals: alloc-free per harness rules)
__device__ float g_pad[HP * WP];   // padded splat canvas
__device__ float g_tmp[HP * OW];   // after horizontal pass (only needed output cols)
__device__ float g_h[KW];          // 1-D separable real-space kernel

// ---------------------------------------------------------------------------
// 1) Exact 1-D DFT kernel: h[t] = (1/WP) * sum_j exp(-k_j^2/(2 sig^2)) cos(2 pi j t / WP)
//    (separable factor of the 2-D transfer function; HP == WP so same for both axes)
// ---------------------------------------------------------------------------
__global__ void kh_kernel() {
    __shared__ double red[256];
    const int u = blockIdx.x;          // 0..KW-1
    int o = u - RAD; if (o < 0) o = -o;
    double acc = 0.0;
    for (int j = threadIdx.x; j < WP; j += 256) {
        int f = (j < WP / 2) ? j : j - WP;          // fftfreq numerator
        double k = (double)f / (double)WP;
        double p = exp(-(k * k) / (2.0 * SIG * SIG));
        int m = (int)(((long long)j * (long long)o) % WP);  // exact phase reduction
        acc += p * cos(2.0 * M_PI * (double)m / (double)WP);
    }
    red[threadIdx.x] = acc;
    __syncthreads();
    for (int s = 128; s > 0; s >>= 1) {
        if (threadIdx.x < s) red[threadIdx.x] += red[threadIdx.x + s];
        __syncthreads();
    }
    if (threadIdx.x == 0) g_h[u] = (float)(red[0] / (double)WP);
}

// ---------------------------------------------------------------------------
// 2) Zero the canvas (vectorized; HP*WP divisible by 4)
// ---------------------------------------------------------------------------
__global__ void zero_kernel() {
    const int n4 = (HP * WP) / 4;
    float4* p = reinterpret_cast<float4*>(g_pad);
    for (int i = blockIdx.x * blockDim.x + threadIdx.x; i < n4; i += gridDim.x * blockDim.x)
        p[i] = make_float4(0.f, 0.f, 0.f, 0.f);
}

// ---------------------------------------------------------------------------
// 3) Bilinear scatter-add splat
// ---------------------------------------------------------------------------
__global__ void splat_kernel(const float2* __restrict__ pos,
                             const float*  __restrict__ inten, int n) {
    int i = blockIdx.x * blockDim.x + threadIdx.x;
    if (i >= n) return;
    float2 p  = pos[i];
    float px = p.x + (float)MARG;
    float py = p.y + (float)MARG;
    int cx = (int)floorf(px);
    int cy = (int)floorf(py);
    cx = min(max(cx, 0), WP - 1);
    cy = min(max(cy, 0), HP - 1);
    float dx = px - (float)cx;
    float dy = py - (float)cy;
    int cx1 = cx + 1; if (cx1 >= WP) cx1 = 0;
    int cy1 = cy + 1; if (cy1 >= HP) cy1 = 0;
    float I = inten[i];
    float w00 = (1.f - dy) * (1.f - dx) * I;
    float w10 = dy * (1.f - dx) * I;
    float w01 = (1.f - dy) * dx * I;
    float w11 = dy * dx * I;
    atomicAdd(&g_pad[cy  * WP + cx ], w00);
    atomicAdd(&g_pad[cy1 * WP + cx ], w10);
    atomicAdd(&g_pad[cy  * WP + cx1], w01);
    atomicAdd(&g_pad[cy1 * WP + cx1], w11);
}

// ---------------------------------------------------------------------------
// 4) Horizontal circular conv: tmp[y][c] = sum_u h[u] * pad[y][(c+MARG + (u-RAD)) mod WP]
//    (h symmetric so tap order is interchangeable)
// ---------------------------------------------------------------------------
__global__ void hconv_kernel() {
    __shared__ float s[256 + 2 * RAD];
    __shared__ float hh[KW];
    const int y  = blockIdx.y;
    const int c0 = blockIdx.x * 256;
    const int t  = threadIdx.x;
    if (t < KW) hh[t] = g_h[t];
    // load window pad[y][c0+MARG-RAD .. c0+MARG-RAD+287] with wrap
    for (int i = t; i < 256 + 2 * RAD; i += 256) {
        int x = c0 + MARG - RAD + i;
        if (x < 0)   x += WP;
        if (x >= WP) x -= WP;
        s[i] = g_pad[y * WP + x];
    }
    __syncthreads();
    float acc = 0.f;
#pragma unroll
    for (int u = 0; u < KW; u++)
        acc = fmaf(hh[u], s[t + u], acc);
    g_tmp[y * OW + c0 + t] = acc;
}

// ---------------------------------------------------------------------------
// 5) Vertical circular conv + crop: out[r][c] = sum_u h[u] * tmp[(r+MARG+(u-RAD)) mod HP][c]
//    tile: 32 cols x 32 out rows; smem (32+2R) x 32
// ---------------------------------------------------------------------------
__global__ void vconv_kernel(float* __restrict__ out) {
    __shared__ float s[32 + 2 * RAD][32];
    __shared__ float hh[KW];
    const int c0 = blockIdx.x * 32;
    const int r0 = blockIdx.y * 32;
    const int tx = threadIdx.x;
    const int ty = threadIdx.y;
    const int lt = ty * 32 + tx;
    if (lt < KW) hh[lt] = g_h[lt];
    // load tmp rows r0+MARG-RAD .. r0+MARG-RAD+63 (wrap mod HP), cols c0..c0+31
    for (int idx = lt; idx < (32 + 2 * RAD) * 32; idx += 256) {
        int row = idx >> 5;
        int col = idx & 31;
        int pr = r0 + MARG - RAD + row;
        if (pr < 0)   pr += HP;
        if (pr >= HP) pr -= HP;
        s[row][col] = g_tmp[pr * OW + c0 + col];
    }
    __syncthreads();
#pragma unroll
    for (int q = 0; q < 4; q++) {
        int lr = ty + 8 * q;             // local out row 0..31
        float acc = 0.f;
#pragma unroll
        for (int u = 0; u < KW; u++)
            acc = fmaf(hh[u], s[lr + u][tx], acc);
        out[(r0 + lr) * OW + c0 + tx] = acc;
    }
}

// ---------------------------------------------------------------------------
extern "C" void kernel_launch(void* const* d_in, const int* in_sizes, int n_in,
                              void* d_out, int out_size) {
    const float2* pos   = (const float2*)d_in[0];   // (N,2) float32 (x, y)
    const float*  inten = (const float*) d_in[1];   // (N,) float32
    const int n = in_sizes[1];
    float* out = (float*)d_out;

    kh_kernel<<<KW, 256>>>();
    zero_kernel<<<1184, 256>>>();                   // 8 blocks/SM-ish grid-stride
    splat_kernel<<<(n + 255) / 256, 256>>>(pos, inten, n);
    hconv_kernel<<<dim3(OW / 256, HP), 256>>>();
    vconv_kernel<<<dim3(OW / 32, OH / 32), dim3(32, 8)>>>(out);
}

// round 8
// speedup vs baseline: 1.3880x; 1.3880x over previous
#include <cuda_runtime.h>
#include <math.h>

// Problem constants (fixed by reference_code)
#define HP   2080            // padded height = H + 2*margin
#define WP   2080            // padded width
#define OW   2048            // output width
#define OH   2048            // output height
#define MARG 16
#define RAD  16              // truncation radius; NOTE MARG==RAD => no circular wrap ever
#define KW   (2*RAD + 1)     // 33 taps
#define SIG  0.05

// Scratch (device globals: alloc-free per harness rules)
__device__ float g_pad[HP * WP];   // padded splat canvas
__device__ float g_tmp[HP * OW];   // after horizontal pass (only output cols kept)
__device__ float g_h[KW];          // 1-D separable real-space kernel

// ---------------------------------------------------------------------------
// 1) Exact 1-D DFT kernel: h[t] = (1/WP) * sum_j exp(-k_j^2/(2 sig^2)) cos(2 pi j t / WP)
// ---------------------------------------------------------------------------
__global__ void kh_kernel() {
    __shared__ double red[256];
    const int u = blockIdx.x;          // 0..KW-1
    int o = u - RAD; if (o < 0) o = -o;
    double acc = 0.0;
    for (int j = threadIdx.x; j < WP; j += 256) {
        int f = (j < WP / 2) ? j : j - WP;          // fftfreq numerator
        double k = (double)f / (double)WP;
        double p = exp(-(k * k) / (2.0 * SIG * SIG));
        int m = (int)(((long long)j * (long long)o) % WP);  // exact phase reduction
        acc += p * cos(2.0 * M_PI * (double)m / (double)WP);
    }
    red[threadIdx.x] = acc;
    __syncthreads();
    for (int s = 128; s > 0; s >>= 1) {
        if (threadIdx.x < s) red[threadIdx.x] += red[threadIdx.x + s];
        __syncthreads();
    }
    if (threadIdx.x == 0) g_h[u] = (float)(red[0] / (double)WP);
}

// ---------------------------------------------------------------------------
// 2) Zero the canvas (vectorized)
// ---------------------------------------------------------------------------
__global__ void zero_kernel() {
    const int n4 = (HP * WP) / 4;
    float4* p = reinterpret_cast<float4*>(g_pad);
    for (int i = blockIdx.x * blockDim.x + threadIdx.x; i < n4; i += gridDim.x * blockDim.x)
        p[i] = make_float4(0.f, 0.f, 0.f, 0.f);
}

// ---------------------------------------------------------------------------
// 3) Bilinear scatter-add splat. Vector float2 atomics when the (cx,cx+1)
//    pair is 8B-aligned (cx even; wrap case cx=WP-1 is odd so falls through).
// ---------------------------------------------------------------------------
__global__ void splat_kernel(const float2* __restrict__ pos,
                             const float*  __restrict__ inten, int n) {
    int i = blockIdx.x * blockDim.x + threadIdx.x;
    if (i >= n) return;
    float2 p  = pos[i];
    float px = p.x + (float)MARG;
    float py = p.y + (float)MARG;
    int cx = (int)floorf(px);
    int cy = (int)floorf(py);
    cx = min(max(cx, 0), WP - 1);
    cy = min(max(cy, 0), HP - 1);
    float dx = px - (float)cx;
    float dy = py - (float)cy;
    int cy1 = cy + 1; if (cy1 >= HP) cy1 = 0;
    float I = inten[i];
    float w00 = (1.f - dy) * (1.f - dx) * I;
    float w10 = dy * (1.f - dx) * I;
    float w01 = (1.f - dy) * dx * I;
    float w11 = dy * dx * I;
#if __CUDA_ARCH__ >= 900
    if ((cx & 1) == 0) {       // cx even => cx+1 valid (no wrap) and 8B aligned
        atomicAdd(reinterpret_cast<float2*>(&g_pad[cy  * WP + cx]), make_float2(w00, w01));
        atomicAdd(reinterpret_cast<float2*>(&g_pad[cy1 * WP + cx]), make_float2(w10, w11));
        return;
    }
#endif
    int cx1 = cx + 1; if (cx1 >= WP) cx1 = 0;
    atomicAdd(&g_pad[cy  * WP + cx ], w00);
    atomicAdd(&g_pad[cy1 * WP + cx ], w10);
    atomicAdd(&g_pad[cy  * WP + cx1], w01);
    atomicAdd(&g_pad[cy1 * WP + cx1], w11);
}

// ---------------------------------------------------------------------------
// 4) Horizontal conv, register-sliding window, 8 outputs/thread.
//    tmp[y][c] = sum_u h[u] * pad[y][c+u]   (MARG-RAD==0, c+u <= 2079 < WP)
//    One block per row; full 2080-float row staged in smem.
// ---------------------------------------------------------------------------
__global__ void __launch_bounds__(256) hconv_kernel() {
    __shared__ float s[WP];            // 2080 floats = 8320 B
    __shared__ float hh[KW];
    const int y = blockIdx.x;
    const int t = threadIdx.x;
    if (t < KW) hh[t] = g_h[t];
    const float4* src = reinterpret_cast<const float4*>(g_pad + y * WP);
    float4* s4 = reinterpret_cast<float4*>(s);
#pragma unroll
    for (int i = t; i < WP / 4; i += 256) s4[i] = src[i];
    __syncthreads();

    // Window pad[y][8t .. 8t+39] as 10 x LDS.128
    float x[40];
#pragma unroll
    for (int m = 0; m < 10; m++) {
        float4 v = s4[2 * t + m];
        x[4 * m + 0] = v.x; x[4 * m + 1] = v.y;
        x[4 * m + 2] = v.z; x[4 * m + 3] = v.w;
    }
    float a0=0.f,a1=0.f,a2=0.f,a3=0.f,a4=0.f,a5=0.f,a6=0.f,a7=0.f;
#pragma unroll
    for (int u = 0; u < KW; u++) {
        float hv = hh[u];
        a0 = fmaf(hv, x[u + 0], a0);
        a1 = fmaf(hv, x[u + 1], a1);
        a2 = fmaf(hv, x[u + 2], a2);
        a3 = fmaf(hv, x[u + 3], a3);
        a4 = fmaf(hv, x[u + 4], a4);
        a5 = fmaf(hv, x[u + 5], a5);
        a6 = fmaf(hv, x[u + 6], a6);
        a7 = fmaf(hv, x[u + 7], a7);
    }
    float4* dst = reinterpret_cast<float4*>(g_tmp + y * OW + 8 * t);
    dst[0] = make_float4(a0, a1, a2, a3);
    dst[1] = make_float4(a4, a5, a6, a7);
}

// ---------------------------------------------------------------------------
// 5) Vertical conv + crop, register-sliding window, 8 outputs/thread.
//    out[r][c] = sum_u h[u] * tmp[r+u][c]   (r+u <= 2079)
//    Tile: 32 cols x 64 out rows; smem (64+32) x 32.
// ---------------------------------------------------------------------------
__global__ void __launch_bounds__(256) vconv_kernel(float* __restrict__ out) {
    __shared__ float s[64 + 2 * RAD][32];   // 96 x 32 = 12 KB
    __shared__ float hh[KW];
    const int c0 = blockIdx.x * 32;
    const int r0 = blockIdx.y * 64;
    const int tx = threadIdx.x;
    const int ty = threadIdx.y;
    const int lt = ty * 32 + tx;
    if (lt < KW) hh[lt] = g_h[lt];
    // Load tmp rows r0..r0+95, cols c0..c0+31 (r0 max 1984 -> row max 2079, in range)
    float4* s4 = reinterpret_cast<float4*>(&s[0][0]);
#pragma unroll
    for (int idx = lt; idx < 96 * 8; idx += 256) {
        int row = idx >> 3;
        int c4  = idx & 7;
        s4[idx] = *reinterpret_cast<const float4*>(g_tmp + (r0 + row) * OW + c0 + 4 * c4);
    }
    __syncthreads();

    // Window: rows ty*8 .. ty*8+39 at column tx (conflict-free, stride-1 across tx)
    float x[40];
#pragma unroll
    for (int k = 0; k < 40; k++) x[k] = s[ty * 8 + k][tx];

    float a0=0.f,a1=0.f,a2=0.f,a3=0.f,a4=0.f,a5=0.f,a6=0.f,a7=0.f;
#pragma unroll
    for (int u = 0; u < KW; u++) {
        float hv = hh[u];
        a0 = fmaf(hv, x[u + 0], a0);
        a1 = fmaf(hv, x[u + 1], a1);
        a2 = fmaf(hv, x[u + 2], a2);
        a3 = fmaf(hv, x[u + 3], a3);
        a4 = fmaf(hv, x[u + 4], a4);
        a5 = fmaf(hv, x[u + 5], a5);
        a6 = fmaf(hv, x[u + 6], a6);
        a7 = fmaf(hv, x[u + 7], a7);
    }
    const int rb = r0 + ty * 8;
    out[(rb + 0) * OW + c0 + tx] = a0;
    out[(rb + 1) * OW + c0 + tx] = a1;
    out[(rb + 2) * OW + c0 + tx] = a2;
    out[(rb + 3) * OW + c0 + tx] = a3;
    out[(rb + 4) * OW + c0 + tx] = a4;
    out[(rb + 5) * OW + c0 + tx] = a5;
    out[(rb + 6) * OW + c0 + tx] = a6;
    out[(rb + 7) * OW + c0 + tx] = a7;
}

// ---------------------------------------------------------------------------
extern "C" void kernel_launch(void* const* d_in, const int* in_sizes, int n_in,
                              void* d_out, int out_size) {
    const float2* pos   = (const float2*)d_in[0];   // (N,2) float32 (x, y)
    const float*  inten = (const float*) d_in[1];   // (N,) float32
    const int n = in_sizes[1];
    float* out = (float*)d_out;

    kh_kernel<<<KW, 256>>>();
    zero_kernel<<<1184, 256>>>();
    splat_kernel<<<(n + 255) / 256, 256>>>(pos, inten, n);
    hconv_kernel<<<HP, 256>>>();
    vconv_kernel<<<dim3(OW / 32, OH / 64), dim3(32, 8)>>>(out);
}

// round 9
// speedup vs baseline: 1.4277x; 1.0286x over previous
#include <cuda_runtime.h>
#include <math.h>

// Problem constants (fixed by reference_code)
#define HP   2080            // padded height = H + 2*margin
#define WP   2080            // padded width
#define OW   2048            // output width
#define OH   2048            // output height
#define MARG 16
#define RAD  13              // truncation radius (calibrated: rel_err ~1e-4 << 1e-3)
#define KW   (2*RAD + 1)     // 27 taps
#define OFF  (MARG - RAD)    // 3; window shift, still no circular wrap (OFF >= 0)
#define SIG  0.05

// Scratch (device globals: alloc-free per harness rules)
__device__ float g_pad[HP * WP];   // padded splat canvas
__device__ float g_tmp[HP * OW];   // after horizontal pass (only output cols kept)
__device__ float g_h[KW];          // 1-D separable real-space kernel

// ---------------------------------------------------------------------------
// 1) Exact 1-D DFT kernel: h[t] = (1/WP) * sum_j exp(-k_j^2/(2 sig^2)) cos(2 pi j t / WP)
// ---------------------------------------------------------------------------
__global__ void kh_kernel() {
    __shared__ double red[256];
    const int u = blockIdx.x;          // 0..KW-1
    int o = u - RAD; if (o < 0) o = -o;
    double acc = 0.0;
    for (int j = threadIdx.x; j < WP; j += 256) {
        int f = (j < WP / 2) ? j : j - WP;          // fftfreq numerator
        double k = (double)f / (double)WP;
        double p = exp(-(k * k) / (2.0 * SIG * SIG));
        int m = (int)(((long long)j * (long long)o) % WP);  // exact phase reduction
        acc += p * cos(2.0 * M_PI * (double)m / (double)WP);
    }
    red[threadIdx.x] = acc;
    __syncthreads();
    for (int s = 128; s > 0; s >>= 1) {
        if (threadIdx.x < s) red[threadIdx.x] += red[threadIdx.x + s];
        __syncthreads();
    }
    if (threadIdx.x == 0) g_h[u] = (float)(red[0] / (double)WP);
}

// ---------------------------------------------------------------------------
// 2) Zero the canvas (vectorized)
// ---------------------------------------------------------------------------
__global__ void zero_kernel() {
    const int n4 = (HP * WP) / 4;
    float4* p = reinterpret_cast<float4*>(g_pad);
    for (int i = blockIdx.x * blockDim.x + threadIdx.x; i < n4; i += gridDim.x * blockDim.x)
        p[i] = make_float4(0.f, 0.f, 0.f, 0.f);
}

// ---------------------------------------------------------------------------
// 3) Bilinear scatter-add splat.
//    Vector red.v4 covers the (cx, cx+1) pair in ONE 16B-aligned atomic when
//    cx mod 4 <= 2 (75% of points). Wrap case cx=2079 has mod 3 -> scalar path.
//    2 points per thread, vectorized position/intensity loads.
// ---------------------------------------------------------------------------
__device__ __forceinline__ void red4(float* p, float a, float b, float c, float d) {
    asm volatile("red.global.add.v4.f32 [%0], {%1, %2, %3, %4};"
                 :: "l"(p), "f"(a), "f"(b), "f"(c), "f"(d) : "memory");
}

__device__ __forceinline__ void splat_one(float px, float py, float I) {
    px += (float)MARG;
    py += (float)MARG;
    int cx = (int)floorf(px);
    int cy = (int)floorf(py);
    cx = min(max(cx, 0), WP - 1);
    cy = min(max(cy, 0), HP - 1);
    float dx = px - (float)cx;
    float dy = py - (float)cy;
    int cy1 = cy + 1; if (cy1 >= HP) cy1 = 0;
    float w00 = (1.f - dy) * (1.f - dx) * I;
    float w10 = dy * (1.f - dx) * I;
    float w01 = (1.f - dy) * dx * I;
    float w11 = dy * dx * I;
    int off = cx & 3;
    if (off != 3) {
        int base = cx & ~3;                 // 16B aligned, base+3 <= 2078 (no wrap)
        float t0 = (off == 0) ? w00 : 0.f;
        float t1 = (off == 0) ? w01 : ((off == 1) ? w00 : 0.f);
        float t2 = (off == 1) ? w01 : ((off == 2) ? w00 : 0.f);
        float t3 = (off == 2) ? w01 : 0.f;
        red4(&g_pad[cy * WP + base], t0, t1, t2, t3);
        float b0 = (off == 0) ? w10 : 0.f;
        float b1 = (off == 0) ? w11 : ((off == 1) ? w10 : 0.f);
        float b2 = (off == 1) ? w11 : ((off == 2) ? w10 : 0.f);
        float b3 = (off == 2) ? w11 : 0.f;
        red4(&g_pad[cy1 * WP + base], b0, b1, b2, b3);
    } else {
        int cx1 = cx + 1; if (cx1 >= WP) cx1 = 0;
        atomicAdd(&g_pad[cy  * WP + cx ], w00);
        atomicAdd(&g_pad[cy1 * WP + cx ], w10);
        atomicAdd(&g_pad[cy  * WP + cx1], w01);
        atomicAdd(&g_pad[cy1 * WP + cx1], w11);
    }
}

__global__ void splat_kernel(const float4* __restrict__ pos4,
                             const float2* __restrict__ inten2, int npair) {
    int i = blockIdx.x * blockDim.x + threadIdx.x;
    if (i >= npair) return;
    float4 q = pos4[i];          // two points: (x0,y0),(x1,y1)
    float2 I = inten2[i];
    splat_one(q.x, q.y, I.x);
    splat_one(q.z, q.w, I.y);
}

// ---------------------------------------------------------------------------
// 4) Horizontal conv, register-sliding window, 8 outputs/thread.
//    tmp[y][c] = sum_u h[u] * pad[y][c + OFF + u]   (max index 8t+7+3+26 <= 2076)
//    One block per row; full 2080-float row staged in smem.
// ---------------------------------------------------------------------------
__global__ void __launch_bounds__(256) hconv_kernel() {
    __shared__ float s[WP];            // 2080 floats = 8320 B
    __shared__ float hh[KW];
    const int y = blockIdx.x;
    const int t = threadIdx.x;
    if (t < KW) hh[t] = g_h[t];
    const float4* src = reinterpret_cast<const float4*>(g_pad + y * WP);
    float4* s4 = reinterpret_cast<float4*>(s);
#pragma unroll
    for (int i = t; i < WP / 4; i += 256) s4[i] = src[i];
    __syncthreads();

    // Window pad[y][8t .. 8t+39] as 10 x LDS.128 (indices OFF..OFF+33 used)
    float x[40];
#pragma unroll
    for (int m = 0; m < 10; m++) {
        float4 v = s4[2 * t + m];
        x[4 * m + 0] = v.x; x[4 * m + 1] = v.y;
        x[4 * m + 2] = v.z; x[4 * m + 3] = v.w;
    }
    float a0=0.f,a1=0.f,a2=0.f,a3=0.f,a4=0.f,a5=0.f,a6=0.f,a7=0.f;
#pragma unroll
    for (int u = 0; u < KW; u++) {
        float hv = hh[u];
        a0 = fmaf(hv, x[u + OFF + 0], a0);
        a1 = fmaf(hv, x[u + OFF + 1], a1);
        a2 = fmaf(hv, x[u + OFF + 2], a2);
        a3 = fmaf(hv, x[u + OFF + 3], a3);
        a4 = fmaf(hv, x[u + OFF + 4], a4);
        a5 = fmaf(hv, x[u + OFF + 5], a5);
        a6 = fmaf(hv, x[u + OFF + 6], a6);
        a7 = fmaf(hv, x[u + OFF + 7], a7);
    }
    float4* dst = reinterpret_cast<float4*>(g_tmp + y * OW + 8 * t);
    dst[0] = make_float4(a0, a1, a2, a3);
    dst[1] = make_float4(a4, a5, a6, a7);
}

// ---------------------------------------------------------------------------
// 5) Vertical conv + crop, register-sliding window, 8 outputs/thread.
//    out[r][c] = sum_u h[u] * tmp[r + OFF + u][c]   (max row 1984+92 = 2076)
//    Tile: 32 cols x 64 out rows; smem rows r0+OFF .. r0+OFF+89.
// ---------------------------------------------------------------------------
#define VROWS (64 + 2 * RAD)   // 90
__global__ void __launch_bounds__(256) vconv_kernel(float* __restrict__ out) {
    __shared__ float s[VROWS][32];     // 90 x 32 = 11.25 KB
    __shared__ float hh[KW];
    const int c0 = blockIdx.x * 32;
    const int r0 = blockIdx.y * 64;
    const int tx = threadIdx.x;
    const int ty = threadIdx.y;
    const int lt = ty * 32 + tx;
    if (lt < KW) hh[lt] = g_h[lt];
    // Load tmp rows r0+OFF .. r0+OFF+VROWS-1, cols c0..c0+31
    float4* s4 = reinterpret_cast<float4*>(&s[0][0]);
#pragma unroll
    for (int idx = lt; idx < VROWS * 8; idx += 256) {
        int row = idx >> 3;
        int c4  = idx & 7;
        s4[idx] = *reinterpret_cast<const float4*>(g_tmp + (r0 + OFF + row) * OW + c0 + 4 * c4);
    }
    __syncthreads();

    // Window: local rows ty*8 .. ty*8+33 at column tx (conflict-free)
    float x[8 + 2 * RAD];              // 34
#pragma unroll
    for (int k = 0; k < 8 + 2 * RAD; k++) x[k] = s[ty * 8 + k][tx];

    float a0=0.f,a1=0.f,a2=0.f,a3=0.f,a4=0.f,a5=0.f,a6=0.f,a7=0.f;
#pragma unroll
    for (int u = 0; u < KW; u++) {
        float hv = hh[u];
        a0 = fmaf(hv, x[u + 0], a0);
        a1 = fmaf(hv, x[u + 1], a1);
        a2 = fmaf(hv, x[u + 2], a2);
        a3 = fmaf(hv, x[u + 3], a3);
        a4 = fmaf(hv, x[u + 4], a4);
        a5 = fmaf(hv, x[u + 5], a5);
        a6 = fmaf(hv, x[u + 6], a6);
        a7 = fmaf(hv, x[u + 7], a7);
    }
    const int rb = r0 + ty * 8;
    out[(rb + 0) * OW + c0 + tx] = a0;
    out[(rb + 1) * OW + c0 + tx] = a1;
    out[(rb + 2) * OW + c0 + tx] = a2;
    out[(rb + 3) * OW + c0 + tx] = a3;
    out[(rb + 4) * OW + c0 + tx] = a4;
    out[(rb + 5) * OW + c0 + tx] = a5;
    out[(rb + 6) * OW + c0 + tx] = a6;
    out[(rb + 7) * OW + c0 + tx] = a7;
}

// ---------------------------------------------------------------------------
extern "C" void kernel_launch(void* const* d_in, const int* in_sizes, int n_in,
                              void* d_out, int out_size) {
    const float4* pos4   = (const float4*)d_in[0];   // (N,2) float32 -> N/2 float4
    const float2* inten2 = (const float2*)d_in[1];   // (N,) float32 -> N/2 float2
    const int n = in_sizes[1];
    const int npair = n / 2;                          // N = 1,000,000 (even)
    float* out = (float*)d_out;

    kh_kernel<<<KW, 256>>>();
    zero_kernel<<<1184, 256>>>();
    splat_kernel<<<(npair + 255) / 256, 256>>>(pos4, inten2, npair);
    hconv_kernel<<<HP, 256>>>();
    vconv_kernel<<<dim3(OW / 32, OH / 64), dim3(32, 8)>>>(out);
}

// round 10
// speedup vs baseline: 1.6123x; 1.1292x over previous
#include <cuda_runtime.h>
#include <math.h>

// Problem constants (fixed by reference_code)
#define HP   2080            // padded height = H + 2*margin
#define WP   2080            // padded width
#define OW   2048            // output width
#define OH   2048            // output height
#define MARG 16
#define RAD  13              // truncation radius (calibrated: rel_err ~4e-5 << 1e-3)
#define KW   (2*RAD + 1)     // 27 taps
#define OFF  (MARG - RAD)    // 3; window shift, no circular wrap needed (OFF >= 0)
#define SIG  0.05f

// Binning for the splat
#define TS     32                       // tile size (pixels)
#define NTX    (WP / TS)                // 65
#define NTILES (NTX * NTX)              // 4225
#define CAP    512                      // slots per bin (mean fill ~237; overflow ~impossible)

// Scratch (device globals: alloc-free per harness rules)
__device__ float  g_pad[HP * WP];       // padded splat canvas
__device__ float  g_tmp[HP * OW];       // after horizontal pass
__device__ float  g_h[KW];              // 1-D separable real-space kernel
__device__ int    g_cnt[NTILES];        // per-tile point counts
__device__ float4 g_bins[NTILES * CAP]; // binned points: (px, py, I, -)

// ---------------------------------------------------------------------------
// 1) Exact 1-D DFT kernel (fp32): h[t] = (1/WP) * sum_j exp(-k^2/(2s^2)) cos(2pi j t/WP)
// ---------------------------------------------------------------------------
__global__ void kh_kernel() {
    __shared__ float red_s[256];
    const int u = blockIdx.x;
    int o = u - RAD; if (o < 0) o = -o;
    float acc = 0.f;
    for (int j = threadIdx.x; j < WP; j += 256) {
        int f = (j < WP / 2) ? j : j - WP;
        float k = (float)f / (float)WP;
        float p = expf(-(k * k) / (2.f * SIG * SIG));
        int m = (j * o) % WP;                       // exact phase reduction
        acc += p * cosf(2.f * (float)M_PI * (float)m / (float)WP);
    }
    red_s[threadIdx.x] = acc;
    __syncthreads();
    for (int s = 128; s > 0; s >>= 1) {
        if (threadIdx.x < s) red_s[threadIdx.x] += red_s[threadIdx.x + s];
        __syncthreads();
    }
    if (threadIdx.x == 0) g_h[u] = red_s[0] / (float)WP;
}

// ---------------------------------------------------------------------------
// 2) Zero canvas + bin counters
// ---------------------------------------------------------------------------
__global__ void zero_kernel() {
    const int n4 = (HP * WP) / 4;
    float4* p = reinterpret_cast<float4*>(g_pad);
    int stride = gridDim.x * blockDim.x;
    for (int i = blockIdx.x * blockDim.x + threadIdx.x; i < n4; i += stride)
        p[i] = make_float4(0.f, 0.f, 0.f, 0.f);
    for (int i = blockIdx.x * blockDim.x + threadIdx.x; i < NTILES; i += stride)
        g_cnt[i] = 0;
}

// ---------------------------------------------------------------------------
// 3a) Scatter points into tile bins. Fallback: direct atomic splat (general-
//     case correct with clamp+wrap; unreachable for this input distribution).
// ---------------------------------------------------------------------------
__global__ void scatter_kernel(const float2* __restrict__ pos,
                               const float*  __restrict__ inten, int n) {
    int i = blockIdx.x * blockDim.x + threadIdx.x;
    if (i >= n) return;
    float2 p = pos[i];
    float px = p.x + (float)MARG;
    float py = p.y + (float)MARG;
    float I  = inten[i];
    int cx = (int)floorf(px);
    int cy = (int)floorf(py);
    cx = min(max(cx, 0), WP - 1);
    cy = min(max(cy, 0), HP - 1);
    int t = (cy >> 5) * NTX + (cx >> 5);
    int idx = atomicAdd(&g_cnt[t], 1);
    if (idx < CAP) {
        g_bins[t * CAP + idx] = make_float4(px, py, I, 0.f);
    } else {
        // overflow fallback: direct scatter
        float dx = px - (float)cx;
        float dy = py - (float)cy;
        int cx1 = cx + 1; if (cx1 >= WP) cx1 = 0;
        int cy1 = cy + 1; if (cy1 >= HP) cy1 = 0;
        atomicAdd(&g_pad[cy  * WP + cx ], (1.f - dy) * (1.f - dx) * I);
        atomicAdd(&g_pad[cy1 * WP + cx ], dy * (1.f - dx) * I);
        atomicAdd(&g_pad[cy  * WP + cx1], (1.f - dy) * dx * I);
        atomicAdd(&g_pad[cy1 * WP + cx1], dy * dx * I);
    }
}

// ---------------------------------------------------------------------------
// 3b) Per-tile accumulation in shared memory, then coalesced add to canvas.
//     Tile covers canvas rows [r0, r0+TS], cols [c0, c0+TS] inclusive (33x33
//     with the bilinear +1 halo).
// ---------------------------------------------------------------------------
#define ACC (TS + 1)   // 33
__global__ void __launch_bounds__(256) accum_kernel() {
    __shared__ float s[ACC * ACC];      // 1089 floats
    const int t  = blockIdx.x;
    const int c0 = (t % NTX) * TS;
    const int r0 = (t / NTX) * TS;
    const int lt = threadIdx.x;

    for (int i = lt; i < ACC * ACC; i += 256) s[i] = 0.f;
    __syncthreads();

    int n = g_cnt[t];
    if (n > CAP) n = CAP;
    const float4* bin = &g_bins[t * CAP];
    for (int i = lt; i < n; i += 256) {
        float4 b = bin[i];
        int cx = (int)floorf(b.x);
        int cy = (int)floorf(b.y);
        float dx = b.x - (float)cx;
        float dy = b.y - (float)cy;
        int lx = cx - c0;               // 0..31
        int ly = cy - r0;               // 0..31
        float I = b.z;
        float w00 = (1.f - dy) * (1.f - dx) * I;
        float w10 = dy * (1.f - dx) * I;
        float w01 = (1.f - dy) * dx * I;
        float w11 = dy * dx * I;
        int base = ly * ACC + lx;
        atomicAdd(&s[base],           w00);
        atomicAdd(&s[base + 1],       w01);
        atomicAdd(&s[base + ACC],     w10);
        atomicAdd(&s[base + ACC + 1], w11);
    }
    __syncthreads();

    // Write tile (+halo) to canvas; skip zeros; guard canvas edge (last tile
    // row/col halo lands at 2080 which is out of range and always zero).
    for (int i = lt; i < ACC * ACC; i += 256) {
        float v = s[i];
        if (v != 0.f) {
            int r = r0 + i / ACC;
            int c = c0 + i % ACC;
            if (r < HP && c < WP)
                atomicAdd(&g_pad[r * WP + c], v);
        }
    }
}

// ---------------------------------------------------------------------------
// 4) Horizontal conv, register-sliding window, 8 outputs/thread.
//    tmp[y][c] = sum_u h[u] * pad[y][c + OFF + u]
// ---------------------------------------------------------------------------
__global__ void __launch_bounds__(256) hconv_kernel() {
    __shared__ float s[WP];
    __shared__ float hh[KW];
    const int y = blockIdx.x;
    const int t = threadIdx.x;
    if (t < KW) hh[t] = g_h[t];
    const float4* src = reinterpret_cast<const float4*>(g_pad + y * WP);
    float4* s4 = reinterpret_cast<float4*>(s);
#pragma unroll
    for (int i = t; i < WP / 4; i += 256) s4[i] = src[i];
    __syncthreads();

    float x[40];
#pragma unroll
    for (int m = 0; m < 10; m++) {
        float4 v = s4[2 * t + m];
        x[4 * m + 0] = v.x; x[4 * m + 1] = v.y;
        x[4 * m + 2] = v.z; x[4 * m + 3] = v.w;
    }
    float a0=0.f,a1=0.f,a2=0.f,a3=0.f,a4=0.f,a5=0.f,a6=0.f,a7=0.f;
#pragma unroll
    for (int u = 0; u < KW; u++) {
        float hv = hh[u];
        a0 = fmaf(hv, x[u + OFF + 0], a0);
        a1 = fmaf(hv, x[u + OFF + 1], a1);
        a2 = fmaf(hv, x[u + OFF + 2], a2);
        a3 = fmaf(hv, x[u + OFF + 3], a3);
        a4 = fmaf(hv, x[u + OFF + 4], a4);
        a5 = fmaf(hv, x[u + OFF + 5], a5);
        a6 = fmaf(hv, x[u + OFF + 6], a6);
        a7 = fmaf(hv, x[u + OFF + 7], a7);
    }
    float4* dst = reinterpret_cast<float4*>(g_tmp + y * OW + 8 * t);
    dst[0] = make_float4(a0, a1, a2, a3);
    dst[1] = make_float4(a4, a5, a6, a7);
}

// ---------------------------------------------------------------------------
// 5) Vertical conv + crop, register-sliding window, 8 outputs/thread.
// ---------------------------------------------------------------------------
#define VROWS (64 + 2 * RAD)   // 90
__global__ void __launch_bounds__(256) vconv_kernel(float* __restrict__ out) {
    __shared__ float s[VROWS][32];
    __shared__ float hh[KW];
    const int c0 = blockIdx.x * 32;
    const int r0 = blockIdx.y * 64;
    const int tx = threadIdx.x;
    const int ty = threadIdx.y;
    const int lt = ty * 32 + tx;
    if (lt < KW) hh[lt] = g_h[lt];
    float4* s4 = reinterpret_cast<float4*>(&s[0][0]);
#pragma unroll
    for (int idx = lt; idx < VROWS * 8; idx += 256) {
        int row = idx >> 3;
        int c4  = idx & 7;
        s4[idx] = *reinterpret_cast<const float4*>(g_tmp + (r0 + OFF + row) * OW + c0 + 4 * c4);
    }
    __syncthreads();

    float x[8 + 2 * RAD];
#pragma unroll
    for (int k = 0; k < 8 + 2 * RAD; k++) x[k] = s[ty * 8 + k][tx];

    float a0=0.f,a1=0.f,a2=0.f,a3=0.f,a4=0.f,a5=0.f,a6=0.f,a7=0.f;
#pragma unroll
    for (int u = 0; u < KW; u++) {
        float hv = hh[u];
        a0 = fmaf(hv, x[u + 0], a0);
        a1 = fmaf(hv, x[u + 1], a1);
        a2 = fmaf(hv, x[u + 2], a2);
        a3 = fmaf(hv, x[u + 3], a3);
        a4 = fmaf(hv, x[u + 4], a4);
        a5 = fmaf(hv, x[u + 5], a5);
        a6 = fmaf(hv, x[u + 6], a6);
        a7 = fmaf(hv, x[u + 7], a7);
    }
    const int rb = r0 + ty * 8;
    out[(rb + 0) * OW + c0 + tx] = a0;
    out[(rb + 1) * OW + c0 + tx] = a1;
    out[(rb + 2) * OW + c0 + tx] = a2;
    out[(rb + 3) * OW + c0 + tx] = a3;
    out[(rb + 4) * OW + c0 + tx] = a4;
    out[(rb + 5) * OW + c0 + tx] = a5;
    out[(rb + 6) * OW + c0 + tx] = a6;
    out[(rb + 7) * OW + c0 + tx] = a7;
}

// ---------------------------------------------------------------------------
extern "C" void kernel_launch(void* const* d_in, const int* in_sizes, int n_in,
                              void* d_out, int out_size) {
    const float2* pos   = (const float2*)d_in[0];   // (N,2) float32 (x, y)
    const float*  inten = (const float*) d_in[1];   // (N,) float32
    const int n = in_sizes[1];
    float* out = (float*)d_out;

    kh_kernel<<<KW, 256>>>();
    zero_kernel<<<1184, 256>>>();
    scatter_kernel<<<(n + 255) / 256, 256>>>(pos, inten, n);
    accum_kernel<<<NTILES, 256>>>();
    hconv_kernel<<<HP, 256>>>();
    vconv_kernel<<<dim3(OW / 32, OH / 64), dim3(32, 8)>>>(out);
}

// round 11
// speedup vs baseline: 2.9486x; 1.8289x over previous
#include <cuda_runtime.h>
#include <math.h>

// Problem constants (fixed by reference_code)
#define HP   2080            // padded height = H + 2*margin
#define WP   2080            // padded width
#define OW   2048            // output width
#define OH   2048            // output height
#define MARG 16
#define RAD  12              // truncation radius (erfc model: rel_err ~1.6e-4 << 1e-3)
#define KW   (2*RAD + 1)     // 25 taps
#define OFF  (MARG - RAD)    // 4; no circular wrap needed (OFF >= 0)
#define SIG  0.05f

// Fused-conv tiling
#define TW   64              // output tile (square)
#define HAL  (2*RAD)         // 24
#define IN   (TW + HAL)      // 88 staged rows/cols
#define SSTR 92              // smem row stride (floats), 16B-aligned, conflict-friendly

// Scratch (device globals: alloc-free per harness rules)
__device__ float g_pad[HP * WP];   // padded splat canvas
__device__ float g_h[KW];          // 1-D separable real-space kernel

// ---------------------------------------------------------------------------
// 1) Exact 1-D DFT kernel (fp32): h[t] = (1/WP) sum_j exp(-k^2/(2s^2)) cos(2pi j t/WP)
// ---------------------------------------------------------------------------
__global__ void kh_kernel() {
    __shared__ float red_s[256];
    const int u = blockIdx.x;
    int o = u - RAD; if (o < 0) o = -o;
    float acc = 0.f;
    for (int j = threadIdx.x; j < WP; j += 256) {
        int f = (j < WP / 2) ? j : j - WP;
        float k = (float)f / (float)WP;
        float p = expf(-(k * k) / (2.f * SIG * SIG));
        int m = (j * o) % WP;                       // exact phase reduction
        acc += p * cosf(2.f * (float)M_PI * (float)m / (float)WP);
    }
    red_s[threadIdx.x] = acc;
    __syncthreads();
    for (int s = 128; s > 0; s >>= 1) {
        if (threadIdx.x < s) red_s[threadIdx.x] += red_s[threadIdx.x + s];
        __syncthreads();
    }
    if (threadIdx.x == 0) g_h[u] = red_s[0] / (float)WP;
}

// ---------------------------------------------------------------------------
// 2) Zero canvas
// ---------------------------------------------------------------------------
__global__ void zero_kernel() {
    const int n4 = (HP * WP) / 4;
    float4* p = reinterpret_cast<float4*>(g_pad);
    int stride = gridDim.x * blockDim.x;
    for (int i = blockIdx.x * blockDim.x + threadIdx.x; i < n4; i += stride)
        p[i] = make_float4(0.f, 0.f, 0.f, 0.f);
}

// ---------------------------------------------------------------------------
// 3) Direct bilinear splat with vector reductions.
//    Both row-cells (cx, cx+1) fit one aligned 16B quad when cx%4 != 3
//    (75% of points -> 2 red lanes); spanning case uses 2 quads per row.
// ---------------------------------------------------------------------------
__device__ __forceinline__ void red4(float* p, float a, float b, float c, float d) {
    asm volatile("red.global.add.v4.f32 [%0], {%1, %2, %3, %4};"
                 :: "l"(p), "f"(a), "f"(b), "f"(c), "f"(d) : "memory");
}

__global__ void splat_kernel(const float2* __restrict__ pos,
                             const float*  __restrict__ inten, int n) {
    int i = blockIdx.x * blockDim.x + threadIdx.x;
    if (i >= n) return;
    float2 p = pos[i];
    float px = p.x + (float)MARG;
    float py = p.y + (float)MARG;
    int cx = (int)floorf(px);
    int cy = (int)floorf(py);
    cx = min(max(cx, 0), WP - 1);
    cy = min(max(cy, 0), HP - 1);
    float dx = px - (float)cx;
    float dy = py - (float)cy;
    int cy1 = cy + 1; if (cy1 >= HP) cy1 = 0;
    float I = inten[i];
    float w00 = (1.f - dy) * (1.f - dx) * I;
    float w01 = (1.f - dy) * dx * I;
    float w10 = dy * (1.f - dx) * I;
    float w11 = dy * dx * I;
    int ra = cy  * WP;
    int rb = cy1 * WP;
    int m4 = cx & 3;
    if (cx < WP - 1) {
        if (m4 != 3) {
            int b = cx & ~3;                // 16B-aligned quad containing cx, cx+1
            float t0 = (m4 == 0) ? w00 : 0.f;
            float t1 = (m4 == 0) ? w01 : ((m4 == 1) ? w00 : 0.f);
            float t2 = (m4 == 1) ? w01 : ((m4 == 2) ? w00 : 0.f);
            float t3 = (m4 == 2) ? w01 : 0.f;
            float b0 = (m4 == 0) ? w10 : 0.f;
            float b1 = (m4 == 0) ? w11 : ((m4 == 1) ? w10 : 0.f);
            float b2 = (m4 == 1) ? w11 : ((m4 == 2) ? w10 : 0.f);
            float b3 = (m4 == 2) ? w11 : 0.f;
            red4(&g_pad[ra + b], t0, t1, t2, t3);
            red4(&g_pad[rb + b], b0, b1, b2, b3);
        } else {                            // cells span two quads (cx%4==3, cx+1%4==0)
            red4(&g_pad[ra + cx - 3], 0.f, 0.f, 0.f, w00);
            red4(&g_pad[ra + cx + 1], w01, 0.f, 0.f, 0.f);
            red4(&g_pad[rb + cx - 3], 0.f, 0.f, 0.f, w10);
            red4(&g_pad[rb + cx + 1], w11, 0.f, 0.f, 0.f);
        }
    } else {                                // cx == WP-1: column wrap (unreachable here)
        atomicAdd(&g_pad[ra + cx], w00);
        atomicAdd(&g_pad[rb + cx], w10);
        atomicAdd(&g_pad[ra], w01);
        atomicAdd(&g_pad[rb], w11);
    }
}

// ---------------------------------------------------------------------------
// 4) Fused separable convolution + crop. One block = one 64x64 output tile.
//    Stage 88x88 canvas region in smem; h-pass into registers (8 outputs per
//    work item), barrier, write back in place; v-pass with 40-float register
//    sliding window, 16 outputs/thread; coalesced stores to d_out.
// ---------------------------------------------------------------------------
__global__ void __launch_bounds__(256) conv_kernel(float* __restrict__ out) {
    __shared__ float s[IN * SSTR];     // 88*92*4 = 32384 B
    __shared__ float hh[KW];
    const int lt = threadIdx.x;
    const int c0 = blockIdx.x * TW;
    const int r0 = blockIdx.y * TW;
    if (lt < KW) hh[lt] = g_h[lt];

    // Stage input: canvas rows r0+OFF .. +87, cols c0+OFF .. +87 (22 float4/row)
    for (int idx = lt; idx < IN * (IN / 4); idx += 256) {
        int row = idx / (IN / 4);
        int c4  = idx % (IN / 4);
        *reinterpret_cast<float4*>(&s[row * SSTR + c4 * 4]) =
            *reinterpret_cast<const float4*>(&g_pad[(r0 + OFF + row) * WP + c0 + OFF + c4 * 4]);
    }
    __syncthreads();

    // h-pass: 88 rows x 8 col-groups = 704 items, 8 outputs each, into registers
    float acc[3][8];
#pragma unroll
    for (int it = 0; it < 3; it++) {
        int w = lt + it * 256;
#pragma unroll
        for (int j = 0; j < 8; j++) acc[it][j] = 0.f;
        if (w < IN * 8) {
            int row = w >> 3;
            int g   = w & 7;
            float x[32];
#pragma unroll
            for (int m = 0; m < 8; m++) {
                float4 v = *reinterpret_cast<float4*>(&s[row * SSTR + g * 8 + m * 4]);
                x[4 * m + 0] = v.x; x[4 * m + 1] = v.y;
                x[4 * m + 2] = v.z; x[4 * m + 3] = v.w;
            }
#pragma unroll
            for (int u = 0; u < KW; u++) {
                float hv = hh[u];
#pragma unroll
                for (int j = 0; j < 8; j++)
                    acc[it][j] = fmaf(hv, x[u + j], acc[it][j]);
            }
        }
    }
    __syncthreads();

    // Write h-pass results back in place (cols 0..63 of each staged row)
#pragma unroll
    for (int it = 0; it < 3; it++) {
        int w = lt + it * 256;
        if (w < IN * 8) {
            int row = w >> 3;
            int g   = w & 7;
            *reinterpret_cast<float4*>(&s[row * SSTR + g * 8]) =
                make_float4(acc[it][0], acc[it][1], acc[it][2], acc[it][3]);
            *reinterpret_cast<float4*>(&s[row * SSTR + g * 8 + 4]) =
                make_float4(acc[it][4], acc[it][5], acc[it][6], acc[it][7]);
        }
    }
    __syncthreads();

    // v-pass: thread (tx, ty) -> output col c0+tx, rows r0+ty*16 .. +15
    const int tx = lt & 63;
    const int ty = lt >> 6;
    float x[16 + HAL];                 // 40
#pragma unroll
    for (int k = 0; k < 16 + HAL; k++) x[k] = s[(ty * 16 + k) * SSTR + tx];

    float a[16];
#pragma unroll
    for (int i = 0; i < 16; i++) a[i] = 0.f;
#pragma unroll
    for (int u = 0; u < KW; u++) {
        float hv = hh[u];
#pragma unroll
        for (int i = 0; i < 16; i++)
            a[i] = fmaf(hv, x[u + i], a[i]);
    }
#pragma unroll
    for (int i = 0; i < 16; i++)
        out[(r0 + ty * 16 + i) * OW + c0 + tx] = a[i];
}

// ---------------------------------------------------------------------------
extern "C" void kernel_launch(void* const* d_in, const int* in_sizes, int n_in,
                              void* d_out, int out_size) {
    const float2* pos   = (const float2*)d_in[0];   // (N,2) float32 (x, y)
    const float*  inten = (const float*) d_in[1];   // (N,) float32
    const int n = in_sizes[1];
    float* out = (float*)d_out;

    kh_kernel<<<KW, 256>>>();
    zero_kernel<<<1184, 256>>>();
    splat_kernel<<<(n + 255) / 256, 256>>>(pos, inten, n);
    conv_kernel<<<dim3(OW / TW, OH / TW), 256>>>(out);
}

// round 12
// speedup vs baseline: 3.2922x; 1.1165x over previous
#include <cuda_runtime.h>
#include <math.h>

// Problem constants (fixed by reference_code)
#define HP   2080            // padded height = H + 2*margin
#define WP   2080            // padded width
#define OW   2048            // output width
#define OH   2048            // output height
#define MARG 16
#define RAD  12              // truncation radius (measured rel_err 1.6e-4 << 1e-3)
#define KW   (2*RAD + 1)     // 25 taps
#define OFF  (MARG - RAD)    // 4; no circular wrap needed (OFF >= 0)
#define SIG  0.05f

// Fused-conv tiling: output tile 64 cols x 128 rows, one resident wave
#define TCW  64              // tile cols (output)
#define TRW  128             // tile rows (output)
#define HAL  (2*RAD)         // 24
#define INR  (TRW + HAL)     // 152 staged rows
#define INC  (TCW + HAL)     // 88 staged cols
#define SSTR 92              // smem row stride (floats): 16B aligned, conflict-friendly
#define PH   (INR / 2)       // 76 rows per h-pass phase
#define PITEMS (PH * 8)      // 608 items per phase (exactly 8 col-groups per row)
#define SMEM_CONV (INR * SSTR * 4)   // 55936 B dynamic

// Scratch (device globals: alloc-free per harness rules)
__device__ float g_pad[HP * WP];   // padded splat canvas
__device__ float g_h[KW];          // 1-D separable real-space kernel

// ---------------------------------------------------------------------------
// 1) Fused init: blocks 0..KW-1 compute the exact 1-D DFT taps
//    h[t] = (1/WP) sum_j exp(-k^2/(2s^2)) cos(2pi j t/WP); the rest zero g_pad.
// ---------------------------------------------------------------------------
#define ZBLOCKS 1184
__global__ void init_kernel() {
    if (blockIdx.x < KW) {
        __shared__ float red_s[256];
        const int u = blockIdx.x;
        int o = u - RAD; if (o < 0) o = -o;
        float acc = 0.f;
        for (int j = threadIdx.x; j < WP; j += 256) {
            int f = (j < WP / 2) ? j : j - WP;
            float k = (float)f / (float)WP;
            float p = expf(-(k * k) / (2.f * SIG * SIG));
            int m = (j * o) % WP;                   // exact phase reduction
            acc += p * cosf(2.f * (float)M_PI * (float)m / (float)WP);
        }
        red_s[threadIdx.x] = acc;
        __syncthreads();
        for (int s = 128; s > 0; s >>= 1) {
            if (threadIdx.x < s) red_s[threadIdx.x] += red_s[threadIdx.x + s];
            __syncthreads();
        }
        if (threadIdx.x == 0) g_h[u] = red_s[0] / (float)WP;
    } else {
        const int n4 = (HP * WP) / 4;
        float4* p = reinterpret_cast<float4*>(g_pad);
        int stride = ZBLOCKS * blockDim.x;
        for (int i = (blockIdx.x - KW) * blockDim.x + threadIdx.x; i < n4; i += stride)
            p[i] = make_float4(0.f, 0.f, 0.f, 0.f);
    }
}

// ---------------------------------------------------------------------------
// 2) Direct bilinear splat with vector reductions (2 RED lanes per point when
//    cx%4 != 3, else 4; row pair always two separate lines).
// ---------------------------------------------------------------------------
__device__ __forceinline__ void red4(float* p, float a, float b, float c, float d) {
    asm volatile("red.global.add.v4.f32 [%0], {%1, %2, %3, %4};"
                 :: "l"(p), "f"(a), "f"(b), "f"(c), "f"(d) : "memory");
}

__global__ void splat_kernel(const float2* __restrict__ pos,
                             const float*  __restrict__ inten, int n) {
    int i = blockIdx.x * blockDim.x + threadIdx.x;
    if (i >= n) return;
    float2 p = pos[i];
    float px = p.x + (float)MARG;
    float py = p.y + (float)MARG;
    int cx = (int)floorf(px);
    int cy = (int)floorf(py);
    cx = min(max(cx, 0), WP - 1);
    cy = min(max(cy, 0), HP - 1);
    float dx = px - (float)cx;
    float dy = py - (float)cy;
    int cy1 = cy + 1; if (cy1 >= HP) cy1 = 0;
    float I = inten[i];
    float w00 = (1.f - dy) * (1.f - dx) * I;
    float w01 = (1.f - dy) * dx * I;
    float w10 = dy * (1.f - dx) * I;
    float w11 = dy * dx * I;
    int ra = cy  * WP;
    int rb = cy1 * WP;
    int m4 = cx & 3;
    if (cx < WP - 1) {
        if (m4 != 3) {
            int b = cx & ~3;                // aligned quad containing cx, cx+1
            float t0 = (m4 == 0) ? w00 : 0.f;
            float t1 = (m4 == 0) ? w01 : ((m4 == 1) ? w00 : 0.f);
            float t2 = (m4 == 1) ? w01 : ((m4 == 2) ? w00 : 0.f);
            float t3 = (m4 == 2) ? w01 : 0.f;
            float b0 = (m4 == 0) ? w10 : 0.f;
            float b1 = (m4 == 0) ? w11 : ((m4 == 1) ? w10 : 0.f);
            float b2 = (m4 == 1) ? w11 : ((m4 == 2) ? w10 : 0.f);
            float b3 = (m4 == 2) ? w11 : 0.f;
            red4(&g_pad[ra + b], t0, t1, t2, t3);
            red4(&g_pad[rb + b], b0, b1, b2, b3);
        } else {                            // spans two quads
            red4(&g_pad[ra + cx - 3], 0.f, 0.f, 0.f, w00);
            red4(&g_pad[ra + cx + 1], w01, 0.f, 0.f, 0.f);
            red4(&g_pad[rb + cx - 3], 0.f, 0.f, 0.f, w10);
            red4(&g_pad[rb + cx + 1], w11, 0.f, 0.f, 0.f);
        }
    } else {                                // column wrap (unreachable here)
        atomicAdd(&g_pad[ra + cx], w00);
        atomicAdd(&g_pad[rb + cx], w10);
        atomicAdd(&g_pad[ra], w01);
        atomicAdd(&g_pad[rb], w11);
    }
}

// ---------------------------------------------------------------------------
// 3) Fused separable convolution + crop. One block = 64x128 output tile.
//    Stage 152x88 in dynamic smem; two-phase in-place h-pass (row-disjoint,
//    only 24 acc regs across a barrier); v-pass = 2 x (40-float reg window,
//    16 outputs); single resident wave (512 blocks, 4/SM).
// ---------------------------------------------------------------------------
extern __shared__ float s[];
__global__ void __launch_bounds__(256, 4) conv_kernel(float* __restrict__ out) {
    __shared__ float hh[KW];
    const int lt = threadIdx.x;
    const int c0 = blockIdx.x * TCW;
    const int r0 = blockIdx.y * TRW;
    if (lt < KW) hh[lt] = g_h[lt];

    // Stage: canvas rows r0+OFF .. +151, cols c0+OFF .. +87 (22 float4/row)
    for (int idx = lt; idx < INR * (INC / 4); idx += 256) {
        int row = idx / (INC / 4);
        int c4  = idx % (INC / 4);
        *reinterpret_cast<float4*>(&s[row * SSTR + c4 * 4]) =
            *reinterpret_cast<const float4*>(&g_pad[(r0 + OFF + row) * WP + c0 + OFF + c4 * 4]);
    }
    __syncthreads();

    // h-pass, two row-disjoint phases with in-place writeback.
    // Item mapping: row fastest (w % PH), group = w / PH -> conflict-free LDS.
#pragma unroll
    for (int ph = 0; ph < 2; ph++) {
        float acc[3][8];
#pragma unroll
        for (int it = 0; it < 3; it++) {
            int w = lt + it * 256;
#pragma unroll
            for (int j = 0; j < 8; j++) acc[it][j] = 0.f;
            if (w < PITEMS) {
                int row = ph * PH + (w % PH);
                int g   = w / PH;
                float x[32];
#pragma unroll
                for (int m = 0; m < 8; m++) {
                    float4 v = *reinterpret_cast<float4*>(&s[row * SSTR + g * 8 + m * 4]);
                    x[4 * m + 0] = v.x; x[4 * m + 1] = v.y;
                    x[4 * m + 2] = v.z; x[4 * m + 3] = v.w;
                }
#pragma unroll
                for (int u = 0; u < KW; u++) {
                    float hv = hh[u];
#pragma unroll
                    for (int j = 0; j < 8; j++)
                        acc[it][j] = fmaf(hv, x[u + j], acc[it][j]);
                }
            }
        }
        __syncthreads();
#pragma unroll
        for (int it = 0; it < 3; it++) {
            int w = lt + it * 256;
            if (w < PITEMS) {
                int row = ph * PH + (w % PH);
                int g   = w / PH;
                *reinterpret_cast<float4*>(&s[row * SSTR + g * 8]) =
                    make_float4(acc[it][0], acc[it][1], acc[it][2], acc[it][3]);
                *reinterpret_cast<float4*>(&s[row * SSTR + g * 8 + 4]) =
                    make_float4(acc[it][4], acc[it][5], acc[it][6], acc[it][7]);
            }
        }
        __syncthreads();
    }

    // v-pass: thread -> col c0+tx; two 16-row groups rg = ty, ty+4
    const int tx = lt & 63;
    const int ty = lt >> 6;
#pragma unroll
    for (int q = 0; q < 2; q++) {
        const int rg = ty + 4 * q;          // 0..7
        float x[16 + HAL];                  // 40
#pragma unroll
        for (int k = 0; k < 16 + HAL; k++) x[k] = s[(rg * 16 + k) * SSTR + tx];
        float a[16];
#pragma unroll
        for (int i = 0; i < 16; i++) a[i] = 0.f;
#pragma unroll
        for (int u = 0; u < KW; u++) {
            float hv = hh[u];
#pragma unroll
            for (int i = 0; i < 16; i++)
                a[i] = fmaf(hv, x[u + i], a[i]);
        }
#pragma unroll
        for (int i = 0; i < 16; i++)
            out[(r0 + rg * 16 + i) * OW + c0 + tx] = a[i];
    }
}

// ---------------------------------------------------------------------------
extern "C" void kernel_launch(void* const* d_in, const int* in_sizes, int n_in,
                              void* d_out, int out_size) {
    const float2* pos   = (const float2*)d_in[0];   // (N,2) float32 (x, y)
    const float*  inten = (const float*) d_in[1];   // (N,) float32
    const int n = in_sizes[1];
    float* out = (float*)d_out;

    cudaFuncSetAttribute(conv_kernel, cudaFuncAttributeMaxDynamicSharedMemorySize, SMEM_CONV);

    init_kernel<<<KW + ZBLOCKS, 256>>>();
    splat_kernel<<<(n + 255) / 256, 256>>>(pos, inten, n);
    conv_kernel<<<dim3(OW / TCW, OH / TRW), 256, SMEM_CONV>>>(out);
}

// round 13
// speedup vs baseline: 3.4832x; 1.0580x over previous
#include <cuda_runtime.h>
#include <math.h>

// Problem constants (fixed by reference_code)
#define HP   2080            // padded height = H + 2*margin
#define WP   2080            // padded width
#define OW   2048            // output width
#define OH   2048            // output height
#define MARG 16
#define RAD  12              // truncation radius (measured rel_err 1.6e-4 << 1e-3)
#define KW   (2*RAD + 1)     // 25 taps
#define OFF  (MARG - RAD)    // 4; no circular wrap needed (OFF >= 0)

// Closed-form real-space taps (exact by Poisson summation; images ~e^-2e5):
//   h[t] = SIG*sqrt(2*pi) * exp(-2*pi^2*SIG^2 * t^2)
#define H_A  0.12533141373155003f   // 0.05 * sqrt(2*pi)
#define H_B  0.04934802200544679f   // 2*pi^2*0.05^2

// Fused-conv tiling: output tile 64 cols x 128 rows, one resident wave
#define TCW  64              // tile cols (output)
#define TRW  128             // tile rows (output)
#define HAL  (2*RAD)         // 24
#define INR  (TRW + HAL)     // 152 staged rows
#define INC  (TCW + HAL)     // 88 staged cols
#define SSTR 92              // smem row stride (floats): 16B aligned, conflict-friendly
#define PH   (INR / 2)       // 76 rows per h-pass phase
#define PITEMS (PH * 8)      // 608 items per phase
#define SMEM_CONV (INR * SSTR * 4)   // 55936 B dynamic

// Scratch (device global: alloc-free per harness rules)
__device__ float g_pad[HP * WP];   // padded splat canvas

// ---------------------------------------------------------------------------
// 1) Zero canvas: exactly one wave (1184 blocks x 256 thr, 8 blocks/SM)
// ---------------------------------------------------------------------------
#define ZBLOCKS 1184
__global__ void zero_kernel() {
    const int n4 = (HP * WP) / 4;
    float4* p = reinterpret_cast<float4*>(g_pad);
    const int stride = ZBLOCKS * 256;
    for (int i = blockIdx.x * 256 + threadIdx.x; i < n4; i += stride)
        p[i] = make_float4(0.f, 0.f, 0.f, 0.f);
}

// ---------------------------------------------------------------------------
// 2) Direct bilinear splat, minimal L2 word-adds:
//    cx even      -> 2x red.v2   (2 ops, 4 words)
//    cx % 4 == 1  -> 2x red.v4   (2 ops, 8 words; cells at base+1, base+2)
//    cx % 4 == 3  -> 4x scalar   (4 ops, 4 words; spans quads / wrap-safe)
// ---------------------------------------------------------------------------
__device__ __forceinline__ void red4(float* p, float a, float b, float c, float d) {
    asm volatile("red.global.add.v4.f32 [%0], {%1, %2, %3, %4};"
                 :: "l"(p), "f"(a), "f"(b), "f"(c), "f"(d) : "memory");
}
__device__ __forceinline__ void red2(float* p, float a, float b) {
    asm volatile("red.global.add.v2.f32 [%0], {%1, %2};"
                 :: "l"(p), "f"(a), "f"(b) : "memory");
}

__global__ void splat_kernel(const float2* __restrict__ pos,
                             const float*  __restrict__ inten, int n) {
    int i = blockIdx.x * blockDim.x + threadIdx.x;
    if (i >= n) return;
    float2 p = pos[i];
    float px = p.x + (float)MARG;
    float py = p.y + (float)MARG;
    int cx = (int)floorf(px);
    int cy = (int)floorf(py);
    cx = min(max(cx, 0), WP - 1);
    cy = min(max(cy, 0), HP - 1);
    float dx = px - (float)cx;
    float dy = py - (float)cy;
    int cy1 = cy + 1; if (cy1 >= HP) cy1 = 0;
    float I = inten[i];
    float w00 = (1.f - dy) * (1.f - dx) * I;
    float w01 = (1.f - dy) * dx * I;
    float w10 = dy * (1.f - dx) * I;
    float w11 = dy * dx * I;
    int ra = cy  * WP;
    int rb = cy1 * WP;
    int m4 = cx & 3;
    if ((cx & 1) == 0) {                    // 8B-aligned pair (cx, cx+1); cx+1 <= 2079
        red2(&g_pad[ra + cx], w00, w01);
        red2(&g_pad[rb + cx], w10, w11);
    } else if (m4 == 1) {                   // cells at quad slots 1,2
        int b = cx & ~3;
        red4(&g_pad[ra + b], 0.f, w00, w01, 0.f);
        red4(&g_pad[rb + b], 0.f, w10, w11, 0.f);
    } else {                                // m4 == 3: spans quads (incl. wrap cx=2079)
        int cx1 = cx + 1; if (cx1 >= WP) cx1 = 0;
        atomicAdd(&g_pad[ra + cx ], w00);
        atomicAdd(&g_pad[rb + cx ], w10);
        atomicAdd(&g_pad[ra + cx1], w01);
        atomicAdd(&g_pad[rb + cx1], w11);
    }
}

// ---------------------------------------------------------------------------
// 3) Fused separable convolution + crop. One block = 64x128 output tile.
//    Taps computed inline (closed form). Stage 152x88 in dynamic smem;
//    two-phase in-place h-pass; v-pass 2 x (40-float reg window, 16 outputs).
//    512 blocks at 4/SM -> single resident wave.
// ---------------------------------------------------------------------------
extern __shared__ float s[];
__global__ void __launch_bounds__(256, 4) conv_kernel(float* __restrict__ out) {
    __shared__ float hh[KW];
    const int lt = threadIdx.x;
    const int c0 = blockIdx.x * TCW;
    const int r0 = blockIdx.y * TRW;
    if (lt < KW) {
        float t = (float)(lt - RAD);
        hh[lt] = H_A * expf(-H_B * t * t);
    }

    // Stage: canvas rows r0+OFF .. +151, cols c0+OFF .. +87 (22 float4/row)
    for (int idx = lt; idx < INR * (INC / 4); idx += 256) {
        int row = idx / (INC / 4);
        int c4  = idx % (INC / 4);
        *reinterpret_cast<float4*>(&s[row * SSTR + c4 * 4]) =
            *reinterpret_cast<const float4*>(&g_pad[(r0 + OFF + row) * WP + c0 + OFF + c4 * 4]);
    }
    __syncthreads();

    // h-pass, two row-disjoint phases with in-place writeback.
#pragma unroll
    for (int ph = 0; ph < 2; ph++) {
        float acc[3][8];
#pragma unroll
        for (int it = 0; it < 3; it++) {
            int w = lt + it * 256;
#pragma unroll
            for (int j = 0; j < 8; j++) acc[it][j] = 0.f;
            if (w < PITEMS) {
                int row = ph * PH + (w % PH);
                int g   = w / PH;
                float x[32];
#pragma unroll
                for (int m = 0; m < 8; m++) {
                    float4 v = *reinterpret_cast<float4*>(&s[row * SSTR + g * 8 + m * 4]);
                    x[4 * m + 0] = v.x; x[4 * m + 1] = v.y;
                    x[4 * m + 2] = v.z; x[4 * m + 3] = v.w;
                }
#pragma unroll
                for (int u = 0; u < KW; u++) {
                    float hv = hh[u];
#pragma unroll
                    for (int j = 0; j < 8; j++)
                        acc[it][j] = fmaf(hv, x[u + j], acc[it][j]);
                }
            }
        }
        __syncthreads();
#pragma unroll
        for (int it = 0; it < 3; it++) {
            int w = lt + it * 256;
            if (w < PITEMS) {
                int row = ph * PH + (w % PH);
                int g   = w / PH;
                *reinterpret_cast<float4*>(&s[row * SSTR + g * 8]) =
                    make_float4(acc[it][0], acc[it][1], acc[it][2], acc[it][3]);
                *reinterpret_cast<float4*>(&s[row * SSTR + g * 8 + 4]) =
                    make_float4(acc[it][4], acc[it][5], acc[it][6], acc[it][7]);
            }
        }
        __syncthreads();
    }

    // v-pass: thread -> col c0+tx; two 16-row groups rg = ty, ty+4
    const int tx = lt & 63;
    const int ty = lt >> 6;
#pragma unroll
    for (int q = 0; q < 2; q++) {
        const int rg = ty + 4 * q;          // 0..7
        float x[16 + HAL];                  // 40
#pragma unroll
        for (int k = 0; k < 16 + HAL; k++) x[k] = s[(rg * 16 + k) * SSTR + tx];
        float a[16];
#pragma unroll
        for (int i = 0; i < 16; i++) a[i] = 0.f;
#pragma unroll
        for (int u = 0; u < KW; u++) {
            float hv = hh[u];
#pragma unroll
            for (int i = 0; i < 16; i++)
                a[i] = fmaf(hv, x[u + i], a[i]);
        }
#pragma unroll
        for (int i = 0; i < 16; i++)
            out[(r0 + rg * 16 + i) * OW + c0 + tx] = a[i];
    }
}

// ---------------------------------------------------------------------------
extern "C" void kernel_launch(void* const* d_in, const int* in_sizes, int n_in,
                              void* d_out, int out_size) {
    const float2* pos   = (const float2*)d_in[0];   // (N,2) float32 (x, y)
    const float*  inten = (const float*) d_in[1];   // (N,) float32
    const int n = in_sizes[1];
    float* out = (float*)d_out;

    cudaFuncSetAttribute(conv_kernel, cudaFuncAttributeMaxDynamicSharedMemorySize, SMEM_CONV);

    zero_kernel<<<ZBLOCKS, 256>>>();
    splat_kernel<<<(n + 255) / 256, 256>>>(pos, inten, n);
    conv_kernel<<<dim3(OW / TCW, OH / TRW), 256, SMEM_CONV>>>(out);
}